// round 14
// baseline (speedup 1.0000x reference)
#include <cuda_runtime.h>
#include <cuda_bf16.h>
#include <mma.h>
#include <cstdint>

using namespace nvcuda;

#define N_NODES 50000
#define N_EDGES 800000
#define CH 128
#define SCAN_CHUNK 512
#define SCAN_BLOCKS ((N_NODES + SCAN_CHUNK - 1) / SCAN_CHUNK)   // 98

// ---------------- scratch (static device globals; no runtime alloc) ----------------
__device__ float g_featA[N_NODES * CH];
__device__ float g_featB[N_NODES * CH];
__device__ int   g_deg[N_NODES];
__device__ int   g_start[N_NODES];
__device__ int   g_cursor[N_NODES];
__device__ int   g_src[N_EDGES];
__device__ unsigned int g_scan_state[SCAN_BLOCKS];  // packed (val<<2)|flag
__device__ int   g_is64;

// ---------------- init: block 0 detects layout + zeroes scan state; rest zero g_deg --
__global__ void init_kernel(const int* __restrict__ ei32) {
    if (blockIdx.x == 0) {
        __shared__ int any_nz;
        if (threadIdx.x == 0) any_nz = 0;
        __syncthreads();
        for (int i = threadIdx.x; i < 4096; i += blockDim.x)
            if (ei32[2 * i + 1] != 0) any_nz = 1;    // benign race
        __syncthreads();
        if (threadIdx.x == 0) g_is64 = any_nz ? 0 : 1;
        for (int i = threadIdx.x; i < SCAN_BLOCKS; i += blockDim.x)
            g_scan_state[i] = 0u;
    } else {
        int i = (blockIdx.x - 1) * blockDim.x + threadIdx.x;
        if (i < N_NODES) g_deg[i] = 0;
    }
}

__device__ __forceinline__ int load_idx(const int* ei32, long long pos) {
    int v = g_is64 ? ei32[2 * pos] : ei32[pos];
    if (v < 0 || v >= N_NODES) v = 0;
    return v;
}

__global__ void hist_kernel(const int* __restrict__ ei32) {
    int e = blockIdx.x * blockDim.x + threadIdx.x;
    if (e < N_EDGES) atomicAdd(&g_deg[load_idx(ei32, (long long)N_EDGES + e)], 1);
}

// ---------------- single-pass decoupled-lookback exclusive scan ----------------
__global__ void scan_kernel() {
    __shared__ int warp_sums[16];
    __shared__ int block_prefix;
    int tid = threadIdx.x, lane = tid & 31, wid = tid >> 5;
    int me = blockIdx.x;
    int i = me * SCAN_CHUNK + tid;
    int v = (i < N_NODES) ? g_deg[i] : 0;
    int val = v;
    #pragma unroll
    for (int off = 1; off < 32; off <<= 1) {
        int t = __shfl_up_sync(0xffffffffu, val, off);
        if (lane >= off) val += t;
    }
    if (lane == 31) warp_sums[wid] = val;
    __syncthreads();
    if (wid == 0) {
        int s = (lane < 16) ? warp_sums[lane] : 0;
        int sv = s;
        #pragma unroll
        for (int off = 1; off < 32; off <<= 1) {
            int t = __shfl_up_sync(0xffffffffu, sv, off);
            if (lane >= off) sv += t;
        }
        int btotal = __shfl_sync(0xffffffffu, sv, 15);
        if (lane < 16) warp_sums[lane] = sv - s;
        if (lane == 0) {
            unsigned pack = ((unsigned)btotal << 2) | (me == 0 ? 2u : 1u);
            atomicExch(&g_scan_state[me], pack);
        }
        int running = 0;
        if (me > 0) {
            int base = me - 1;
            while (true) {
                int p = base - lane;
                int flag = 0, pv = 0;
                if (p >= 0) {
                    unsigned s2;
                    do { s2 = *(volatile unsigned int*)&g_scan_state[p]; } while ((s2 & 3u) == 0u);
                    flag = (int)(s2 & 3u);
                    pv   = (int)(s2 >> 2);
                }
                unsigned pm = __ballot_sync(0xffffffffu, flag == 2);
                if (pm) {
                    int L = __ffs(pm) - 1;
                    int contrib = (lane <= L) ? pv : 0;
                    #pragma unroll
                    for (int o = 16; o; o >>= 1) contrib += __shfl_xor_sync(0xffffffffu, contrib, o);
                    running += contrib;
                    break;
                } else {
                    int contrib = (p >= 0) ? pv : 0;
                    #pragma unroll
                    for (int o = 16; o; o >>= 1) contrib += __shfl_xor_sync(0xffffffffu, contrib, o);
                    running += contrib;
                    base -= 32;
                }
            }
            if (lane == 0) {
                unsigned pack = (((unsigned)(running + btotal)) << 2) | 2u;
                atomicExch(&g_scan_state[me], pack);
            }
        }
        if (lane == 0) block_prefix = running;
    }
    __syncthreads();
    int excl = val - v + warp_sums[wid] + block_prefix;
    if (i < N_NODES) { g_start[i] = excl; g_cursor[i] = excl; }
}

__global__ void fill_kernel(const int* __restrict__ ei32) {
    int e = blockIdx.x * blockDim.x + threadIdx.x;
    if (e < N_EDGES) {
        int d = load_idx(ei32, (long long)N_EDGES + e);
        int s = load_idx(ei32, e);
        int p = atomicAdd(&g_cursor[d], 1);
        if (p >= 0 && p < N_EDGES) g_src[p] = s;
    }
}

// ================= fused SAGE layer: gather-mean + WMMA bf16-split GEMM =============
// out = PReLU( mean_nbr(X) @ Wl^T + bl + X @ Wr^T ).
// Pass 0 A-tile = gather-mean of X rows (computed in fill phase, no g_agg buffer).
// fp32 split x = hi + lo (bf16); acc += hi*hi + hi*lo + lo*hi (fp32 TC accum).
// CTA: 128 M x 128 N; 8 warps (4x2), warp tile 32x64, frags 2x4 of 16x16. K=128/pass.

#define GW_LD   136                      // bf16 per tile row (272 B: ldmatrix conflict-free)
#define GW_TILE (128 * GW_LD * 2)        // 34816 B
#define GW_AHI  0
#define GW_ALO  (GW_TILE)
#define GW_BHI  (2 * GW_TILE)
#define GW_BLO  (3 * GW_TILE)
#define GW_SMEM (4 * GW_TILE)            // 139264 B
#define GW_SLD  132                      // fp32 stage row stride

__device__ __forceinline__ void split_store(__nv_bfloat16* hi, __nv_bfloat16* lo,
                                            int eoff, float4 v) {
    __nv_bfloat16 h0 = __float2bfloat16(v.x);
    __nv_bfloat16 h1 = __float2bfloat16(v.y);
    __nv_bfloat16 h2 = __float2bfloat16(v.z);
    __nv_bfloat16 h3 = __float2bfloat16(v.w);
    __nv_bfloat16 l0 = __float2bfloat16(v.x - __bfloat162float(h0));
    __nv_bfloat16 l1 = __float2bfloat16(v.y - __bfloat162float(h1));
    __nv_bfloat16 l2 = __float2bfloat16(v.z - __bfloat162float(h2));
    __nv_bfloat16 l3 = __float2bfloat16(v.w - __bfloat162float(h3));
    uint2 hv = make_uint2(((uint32_t)__bfloat16_as_ushort(h1) << 16) | __bfloat16_as_ushort(h0),
                          ((uint32_t)__bfloat16_as_ushort(h3) << 16) | __bfloat16_as_ushort(h2));
    uint2 lv = make_uint2(((uint32_t)__bfloat16_as_ushort(l1) << 16) | __bfloat16_as_ushort(l0),
                          ((uint32_t)__bfloat16_as_ushort(l3) << 16) | __bfloat16_as_ushort(l2));
    *(uint2*)(hi + eoff) = hv;
    *(uint2*)(lo + eoff) = lv;
}

__global__ __launch_bounds__(256) void sage_layer_kernel(
    const float* __restrict__ xext, int xsel,
    const float* __restrict__ Wl, const float* __restrict__ bl,
    const float* __restrict__ Wr, const float* __restrict__ pa,
    float* __restrict__ oext, int osel, int M)
{
    extern __shared__ char dsm[];
    const float* X = (xsel == 0) ? xext : ((xsel == 1) ? g_featA : g_featB);
    float*       O = (osel == 0) ? oext : ((osel == 1) ? g_featA : g_featB);

    __nv_bfloat16* Ahi = (__nv_bfloat16*)(dsm + GW_AHI);
    __nv_bfloat16* Alo = (__nv_bfloat16*)(dsm + GW_ALO);
    __nv_bfloat16* Bhi = (__nv_bfloat16*)(dsm + GW_BHI);
    __nv_bfloat16* Blo = (__nv_bfloat16*)(dsm + GW_BLO);

    int tid = threadIdx.x;
    int lane = tid & 31;
    int wid = tid >> 5;
    int warp_m = wid >> 1;    // 0..3 -> rows warp_m*32
    int warp_n = wid & 1;     // 0..1 -> cols warp_n*64
    int block_row = blockIdx.x * 128;
    const float4* xbase = (const float4*)X;

    wmma::fragment<wmma::accumulator, 16, 16, 16, float> acc[2][4];
    #pragma unroll
    for (int i = 0; i < 2; i++)
        #pragma unroll
        for (int j = 0; j < 4; j++) wmma::fill_fragment(acc[i][j], 0.f);

    #pragma unroll 1
    for (int p = 0; p < 2; p++) {
        const float* Wp = p ? Wr : Wl;
        // ---- W tile fill: Bhi/Blo, 4096 float4-groups, 16 per thread ----
        #pragma unroll 4
        for (int it = 0; it < 16; it++) {
            int g  = tid + it * 256;
            int r  = g >> 5;              // 0..127
            int k0 = (g & 31) << 2;       // 0..124
            float4 wv = *(const float4*)(Wp + (size_t)r * CH + k0);
            split_store(Bhi, Blo, r * GW_LD + k0, wv);
        }
        // ---- A tile fill ----
        if (p == 0) {
            // gather-mean: warp handles rows wid*16..+15; lane covers cols lane*4..+3
            for (int rr = 0; rr < 16; rr++) {
                int r = wid * 16 + rr;
                int grow = block_row + r;
                float4 v = make_float4(0.f, 0.f, 0.f, 0.f);
                if (grow < M) {
                    int s = g_start[grow];
                    int n = g_deg[grow];
                    float4 a0 = make_float4(0.f, 0.f, 0.f, 0.f);
                    float4 a1 = make_float4(0.f, 0.f, 0.f, 0.f);
                    int e = 0;
                    for (; e + 1 < n; e += 2) {
                        int s0 = g_src[s + e], s1 = g_src[s + e + 1];
                        float4 v0 = xbase[s0 * 32 + lane];
                        float4 v1 = xbase[s1 * 32 + lane];
                        a0.x += v0.x; a0.y += v0.y; a0.z += v0.z; a0.w += v0.w;
                        a1.x += v1.x; a1.y += v1.y; a1.z += v1.z; a1.w += v1.w;
                    }
                    if (e < n) {
                        float4 v0 = xbase[g_src[s + e] * 32 + lane];
                        a0.x += v0.x; a0.y += v0.y; a0.z += v0.z; a0.w += v0.w;
                    }
                    float inv = (n > 0) ? 1.0f / (float)n : 0.0f;
                    v = make_float4((a0.x + a1.x) * inv, (a0.y + a1.y) * inv,
                                    (a0.z + a1.z) * inv, (a0.w + a1.w) * inv);
                }
                split_store(Ahi, Alo, r * GW_LD + lane * 4, v);
            }
        } else {
            #pragma unroll 4
            for (int it = 0; it < 16; it++) {
                int g  = tid + it * 256;
                int r  = g >> 5;
                int k0 = (g & 31) << 2;
                float4 av = make_float4(0.f, 0.f, 0.f, 0.f);
                if (block_row + r < M)
                    av = *(const float4*)(X + (size_t)(block_row + r) * CH + k0);
                split_store(Ahi, Alo, r * GW_LD + k0, av);
            }
        }
        __syncthreads();

        #pragma unroll 1
        for (int k0 = 0; k0 < 128; k0 += 16) {
            wmma::fragment<wmma::matrix_a, 16, 16, 16, __nv_bfloat16, wmma::row_major> a_hi[2], a_lo[2];
            wmma::fragment<wmma::matrix_b, 16, 16, 16, __nv_bfloat16, wmma::col_major> b_hi[4], b_lo[4];
            #pragma unroll
            for (int i = 0; i < 2; i++) {
                int r0 = warp_m * 32 + i * 16;
                wmma::load_matrix_sync(a_hi[i], Ahi + r0 * GW_LD + k0, GW_LD);
                wmma::load_matrix_sync(a_lo[i], Alo + r0 * GW_LD + k0, GW_LD);
            }
            #pragma unroll
            for (int j = 0; j < 4; j++) {
                int n0 = warp_n * 64 + j * 16;
                wmma::load_matrix_sync(b_hi[j], Bhi + n0 * GW_LD + k0, GW_LD);
                wmma::load_matrix_sync(b_lo[j], Blo + n0 * GW_LD + k0, GW_LD);
            }
            #pragma unroll
            for (int i = 0; i < 2; i++)
                #pragma unroll
                for (int j = 0; j < 4; j++) {
                    wmma::mma_sync(acc[i][j], a_hi[i], b_hi[j], acc[i][j]);
                    wmma::mma_sync(acc[i][j], a_hi[i], b_lo[j], acc[i][j]);
                    wmma::mma_sync(acc[i][j], a_lo[i], b_hi[j], acc[i][j]);
                }
        }
        __syncthreads();   // all reads done before next fill overwrites tiles
    }

    // stage accumulators to SMEM (reuse tile memory), then fused bias+PReLU writeout
    float* stage = (float*)dsm;
    #pragma unroll
    for (int i = 0; i < 2; i++)
        #pragma unroll
        for (int j = 0; j < 4; j++) {
            int r0 = warp_m * 32 + i * 16;
            int n0 = warp_n * 64 + j * 16;
            wmma::store_matrix_sync(stage + r0 * GW_SLD + n0, acc[i][j], GW_SLD,
                                    wmma::mem_row_major);
        }
    __syncthreads();

    #pragma unroll 4
    for (int it = 0; it < 16; it++) {
        int g  = tid + it * 256;
        int r  = g >> 5;
        int c0 = (g & 31) << 2;
        int grow = block_row + r;
        if (grow < M) {
            float4 v  = *(const float4*)(stage + r * GW_SLD + c0);
            float4 bb = *(const float4*)(bl + c0);
            float4 aa = *(const float4*)(pa + c0);
            float v0 = v.x + bb.x, v1 = v.y + bb.y, v2 = v.z + bb.z, v3 = v.w + bb.w;
            float4 o;
            o.x = (v0 > 0.f) ? v0 : aa.x * v0;
            o.y = (v1 > 0.f) ? v1 : aa.y * v1;
            o.z = (v2 > 0.f) ? v2 : aa.z * v2;
            o.w = (v3 > 0.f) ? v3 : aa.w * v3;
            *(float4*)(O + (size_t)grow * CH + c0) = o;
        }
    }
}

// ---------------- launch ----------------
extern "C" void kernel_launch(void* const* d_in, const int* in_sizes, int n_in,
                              void* d_out, int out_size) {
    const float* x    = (const float*)d_in[0];
    const int*   ei32 = (const int*)d_in[1];
    int wb = n_in - 12;                          // weights are the LAST 12 inputs
    const float* Wl0 = (const float*)d_in[wb + 0];
    const float* bl0 = (const float*)d_in[wb + 1];
    const float* Wr0 = (const float*)d_in[wb + 2];
    const float* a0  = (const float*)d_in[wb + 3];
    const float* Wl1 = (const float*)d_in[wb + 4];
    const float* bl1 = (const float*)d_in[wb + 5];
    const float* Wr1 = (const float*)d_in[wb + 6];
    const float* a1  = (const float*)d_in[wb + 7];
    const float* Wl2 = (const float*)d_in[wb + 8];
    const float* bl2 = (const float*)d_in[wb + 9];
    const float* Wr2 = (const float*)d_in[wb + 10];
    const float* a2  = (const float*)d_in[wb + 11];
    float* out = (float*)d_out;

    const int EB = (N_EDGES + 255) / 256;        // 3125
    const int NB = (N_NODES + 255) / 256;        // 196
    const int GM = (N_NODES + 127) / 128;        // 391

    cudaFuncSetAttribute(sage_layer_kernel,
                         cudaFuncAttributeMaxDynamicSharedMemorySize, GW_SMEM);

    // CSR build
    init_kernel<<<NB + 1, 256>>>(ei32);          // #0
    hist_kernel<<<EB, 256>>>(ei32);              // #1
    scan_kernel<<<SCAN_BLOCKS, SCAN_CHUNK>>>();  // #2
    fill_kernel<<<EB, 256>>>(ei32);              // #3

    // Fused layers (gather + GEMM + bias + PReLU in one kernel each)
    sage_layer_kernel<<<GM, 256, GW_SMEM>>>(x, 0, Wl0, bl0, Wr0, a0, nullptr, 1, N_NODES);   // #4
    sage_layer_kernel<<<GM, 256, GW_SMEM>>>(nullptr, 1, Wl1, bl1, Wr1, a1, nullptr, 2, N_NODES); // #5 <- profiled
    sage_layer_kernel<<<1024 / 128, 256, GW_SMEM>>>(nullptr, 2, Wl2, bl2, Wr2, a2, out, 0, 1024); // #6
}

// round 15
// speedup vs baseline: 1.5546x; 1.5546x over previous
#include <cuda_runtime.h>
#include <cuda_bf16.h>
#include <mma.h>
#include <cstdint>

using namespace nvcuda;

#define N_NODES 50000
#define N_EDGES 800000
#define CH 128
#define SCAN_CHUNK 512
#define SCAN_BLOCKS ((N_NODES + SCAN_CHUNK - 1) / SCAN_CHUNK)   // 98

// ---------------- scratch (static device globals; no runtime alloc) ----------------
__device__ float g_featA[N_NODES * CH];
__device__ float g_featB[N_NODES * CH];
__device__ float g_agg[N_NODES * CH];
__device__ int   g_deg[N_NODES];
__device__ int   g_start[N_NODES];
__device__ int   g_cursor[N_NODES];
__device__ int   g_src[N_EDGES];
__device__ unsigned int g_scan_state[SCAN_BLOCKS];  // packed (val<<2)|flag
__device__ int   g_is64;

// ---------------- init: block 0 detects layout + zeroes scan state; rest zero g_deg --
__global__ void init_kernel(const int* __restrict__ ei32) {
    if (blockIdx.x == 0) {
        __shared__ int any_nz;
        if (threadIdx.x == 0) any_nz = 0;
        __syncthreads();
        for (int i = threadIdx.x; i < 4096; i += blockDim.x)
            if (ei32[2 * i + 1] != 0) any_nz = 1;    // benign race
        __syncthreads();
        if (threadIdx.x == 0) g_is64 = any_nz ? 0 : 1;
        for (int i = threadIdx.x; i < SCAN_BLOCKS; i += blockDim.x)
            g_scan_state[i] = 0u;
    } else {
        int i = (blockIdx.x - 1) * blockDim.x + threadIdx.x;
        if (i < N_NODES) g_deg[i] = 0;
    }
}

__device__ __forceinline__ int load_idx(const int* ei32, long long pos) {
    int v = g_is64 ? ei32[2 * pos] : ei32[pos];
    if (v < 0 || v >= N_NODES) v = 0;
    return v;
}

__global__ void hist_kernel(const int* __restrict__ ei32) {
    int e = blockIdx.x * blockDim.x + threadIdx.x;
    if (e < N_EDGES) atomicAdd(&g_deg[load_idx(ei32, (long long)N_EDGES + e)], 1);
}

// ---------------- single-pass decoupled-lookback exclusive scan ----------------
__global__ void scan_kernel() {
    __shared__ int warp_sums[16];
    __shared__ int block_prefix;
    int tid = threadIdx.x, lane = tid & 31, wid = tid >> 5;
    int me = blockIdx.x;
    int i = me * SCAN_CHUNK + tid;
    int v = (i < N_NODES) ? g_deg[i] : 0;
    int val = v;
    #pragma unroll
    for (int off = 1; off < 32; off <<= 1) {
        int t = __shfl_up_sync(0xffffffffu, val, off);
        if (lane >= off) val += t;
    }
    if (lane == 31) warp_sums[wid] = val;
    __syncthreads();
    if (wid == 0) {
        int s = (lane < 16) ? warp_sums[lane] : 0;
        int sv = s;
        #pragma unroll
        for (int off = 1; off < 32; off <<= 1) {
            int t = __shfl_up_sync(0xffffffffu, sv, off);
            if (lane >= off) sv += t;
        }
        int btotal = __shfl_sync(0xffffffffu, sv, 15);
        if (lane < 16) warp_sums[lane] = sv - s;
        if (lane == 0) {
            unsigned pack = ((unsigned)btotal << 2) | (me == 0 ? 2u : 1u);
            atomicExch(&g_scan_state[me], pack);
        }
        int running = 0;
        if (me > 0) {
            int base = me - 1;
            while (true) {
                int p = base - lane;
                int flag = 0, pv = 0;
                if (p >= 0) {
                    unsigned s2;
                    do { s2 = *(volatile unsigned int*)&g_scan_state[p]; } while ((s2 & 3u) == 0u);
                    flag = (int)(s2 & 3u);
                    pv   = (int)(s2 >> 2);
                }
                unsigned pm = __ballot_sync(0xffffffffu, flag == 2);
                if (pm) {
                    int L = __ffs(pm) - 1;
                    int contrib = (lane <= L) ? pv : 0;
                    #pragma unroll
                    for (int o = 16; o; o >>= 1) contrib += __shfl_xor_sync(0xffffffffu, contrib, o);
                    running += contrib;
                    break;
                } else {
                    int contrib = (p >= 0) ? pv : 0;
                    #pragma unroll
                    for (int o = 16; o; o >>= 1) contrib += __shfl_xor_sync(0xffffffffu, contrib, o);
                    running += contrib;
                    base -= 32;
                }
            }
            if (lane == 0) {
                unsigned pack = (((unsigned)(running + btotal)) << 2) | 2u;
                atomicExch(&g_scan_state[me], pack);
            }
        }
        if (lane == 0) block_prefix = running;
    }
    __syncthreads();
    int excl = val - v + warp_sums[wid] + block_prefix;
    if (i < N_NODES) { g_start[i] = excl; g_cursor[i] = excl; }
}

__global__ void fill_kernel(const int* __restrict__ ei32) {
    int e = blockIdx.x * blockDim.x + threadIdx.x;
    if (e < N_EDGES) {
        int d = load_idx(ei32, (long long)N_EDGES + e);
        int s = load_idx(ei32, e);
        int p = atomicAdd(&g_cursor[d], 1);
        if (p >= 0 && p < N_EDGES) g_src[p] = s;
    }
}

// ---------------- mean aggregation: one warp per dst node, MLP-2 unroll -------------
__global__ void agg_kernel(const float* __restrict__ xext, int sel, int nrows) {
    int gw = (int)((blockIdx.x * blockDim.x + threadIdx.x) >> 5);
    int lane = threadIdx.x & 31;
    if (gw >= nrows) return;
    const float* feat = (sel == 0) ? xext : ((sel == 1) ? g_featA : g_featB);
    const float4* base = (const float4*)feat;
    int s = g_start[gw];
    int n = g_deg[gw];
    float4 acc0 = make_float4(0.f, 0.f, 0.f, 0.f);
    float4 acc1 = make_float4(0.f, 0.f, 0.f, 0.f);
    int e = 0;
    for (; e + 1 < n; e += 2) {
        int s0 = g_src[s + e], s1 = g_src[s + e + 1];
        float4 v0 = base[s0 * 32 + lane];
        float4 v1 = base[s1 * 32 + lane];
        acc0.x += v0.x; acc0.y += v0.y; acc0.z += v0.z; acc0.w += v0.w;
        acc1.x += v1.x; acc1.y += v1.y; acc1.z += v1.z; acc1.w += v1.w;
    }
    if (e < n) {
        float4 v = base[g_src[s + e] * 32 + lane];
        acc0.x += v.x; acc0.y += v.y; acc0.z += v.z; acc0.w += v.w;
    }
    float inv = (n > 0) ? 1.0f / (float)n : 0.0f;
    ((float4*)g_agg)[gw * 32 + lane] =
        make_float4((acc0.x + acc1.x) * inv, (acc0.y + acc1.y) * inv,
                    (acc0.z + acc1.z) * inv, (acc0.w + acc1.w) * inv);
}

// ================= WMMA bf16-split GEMM + bias + PReLU =================
// out = PReLU( g_agg @ Wl^T + bl + X @ Wr^T ).
// fp32 split x = hi + lo (bf16); acc += hi*hi + hi*lo + lo*hi (fp32 TC accum).
// CTA: 128 M x 64 N (grid.y = 2 N-halves); 8 warps (4x2), warp tile 32x32,
// frags 2x2 of 16x16. K=128 per pass, 2 passes. 102 KB SMEM -> 2 CTAs/SM:
// one CTA's fill/epilogue overlaps the other's MMA phase.

#define GW_LD    136                     // bf16 per tile row (272 B: ldmatrix conflict-free)
#define GW_ATILE (128 * GW_LD * 2)       // 34816 B
#define GW_BTILE (64 * GW_LD * 2)        // 17408 B
#define GW_AHI   0
#define GW_ALO   (GW_ATILE)
#define GW_BHI   (2 * GW_ATILE)
#define GW_BLO   (2 * GW_ATILE + GW_BTILE)
#define GW_SMEM  (2 * GW_ATILE + 2 * GW_BTILE)   // 104448 B
#define GW_SLD   68                      // fp32 stage row stride (128x68x4 = 34816 B)

__device__ __forceinline__ void split_store(__nv_bfloat16* hi, __nv_bfloat16* lo,
                                            int eoff, float4 v) {
    __nv_bfloat16 h0 = __float2bfloat16(v.x);
    __nv_bfloat16 h1 = __float2bfloat16(v.y);
    __nv_bfloat16 h2 = __float2bfloat16(v.z);
    __nv_bfloat16 h3 = __float2bfloat16(v.w);
    __nv_bfloat16 l0 = __float2bfloat16(v.x - __bfloat162float(h0));
    __nv_bfloat16 l1 = __float2bfloat16(v.y - __bfloat162float(h1));
    __nv_bfloat16 l2 = __float2bfloat16(v.z - __bfloat162float(h2));
    __nv_bfloat16 l3 = __float2bfloat16(v.w - __bfloat162float(h3));
    uint2 hv = make_uint2(((uint32_t)__bfloat16_as_ushort(h1) << 16) | __bfloat16_as_ushort(h0),
                          ((uint32_t)__bfloat16_as_ushort(h3) << 16) | __bfloat16_as_ushort(h2));
    uint2 lv = make_uint2(((uint32_t)__bfloat16_as_ushort(l1) << 16) | __bfloat16_as_ushort(l0),
                          ((uint32_t)__bfloat16_as_ushort(l3) << 16) | __bfloat16_as_ushort(l2));
    *(uint2*)(hi + eoff) = hv;
    *(uint2*)(lo + eoff) = lv;
}

__global__ __launch_bounds__(256, 2) void gemm_wmma_kernel(
    const float* __restrict__ xext, int xsel,
    const float* __restrict__ Wl, const float* __restrict__ bl,
    const float* __restrict__ Wr, const float* __restrict__ pa,
    float* __restrict__ oext, int osel, int M)
{
    extern __shared__ char dsm[];
    const float* X = (xsel == 0) ? xext : ((xsel == 1) ? g_featA : g_featB);
    float*       O = (osel == 0) ? oext : ((osel == 1) ? g_featA : g_featB);

    __nv_bfloat16* Ahi = (__nv_bfloat16*)(dsm + GW_AHI);
    __nv_bfloat16* Alo = (__nv_bfloat16*)(dsm + GW_ALO);
    __nv_bfloat16* Bhi = (__nv_bfloat16*)(dsm + GW_BHI);
    __nv_bfloat16* Blo = (__nv_bfloat16*)(dsm + GW_BLO);

    int tid = threadIdx.x;
    int wid = tid >> 5;
    int warp_m = wid >> 1;                // 0..3 -> rows warp_m*32
    int warp_n = wid & 1;                 // 0..1 -> cols warp_n*32
    int block_row = blockIdx.x * 128;
    int nbase = blockIdx.y * 64;          // N-half of the weight/output

    wmma::fragment<wmma::accumulator, 16, 16, 16, float> acc[2][2];
    #pragma unroll
    for (int i = 0; i < 2; i++)
        #pragma unroll
        for (int j = 0; j < 2; j++) wmma::fill_fragment(acc[i][j], 0.f);

    #pragma unroll 1
    for (int p = 0; p < 2; p++) {
        const float* Ap = p ? X  : g_agg;
        const float* Wp = p ? Wr : Wl;
        // A tile: 4096 float4-groups, 16 per thread
        #pragma unroll 4
        for (int it = 0; it < 16; it++) {
            int g  = tid + it * 256;
            int r  = g >> 5;              // 0..127
            int k0 = (g & 31) << 2;       // 0..124
            float4 av = make_float4(0.f, 0.f, 0.f, 0.f);
            if (block_row + r < M)
                av = *(const float4*)(Ap + (size_t)(block_row + r) * CH + k0);
            split_store(Ahi, Alo, r * GW_LD + k0, av);
        }
        // W tile: rows nbase..nbase+63 -> 2048 groups, 8 per thread
        #pragma unroll 4
        for (int it = 0; it < 8; it++) {
            int g  = tid + it * 256;
            int r  = g >> 5;              // 0..63
            int k0 = (g & 31) << 2;
            float4 wv = *(const float4*)(Wp + (size_t)(nbase + r) * CH + k0);
            split_store(Bhi, Blo, r * GW_LD + k0, wv);
        }
        __syncthreads();

        #pragma unroll 1
        for (int k0 = 0; k0 < 128; k0 += 16) {
            wmma::fragment<wmma::matrix_a, 16, 16, 16, __nv_bfloat16, wmma::row_major> a_hi[2], a_lo[2];
            wmma::fragment<wmma::matrix_b, 16, 16, 16, __nv_bfloat16, wmma::col_major> b_hi[2], b_lo[2];
            #pragma unroll
            for (int i = 0; i < 2; i++) {
                int r0 = warp_m * 32 + i * 16;
                wmma::load_matrix_sync(a_hi[i], Ahi + r0 * GW_LD + k0, GW_LD);
                wmma::load_matrix_sync(a_lo[i], Alo + r0 * GW_LD + k0, GW_LD);
            }
            #pragma unroll
            for (int j = 0; j < 2; j++) {
                int n0 = warp_n * 32 + j * 16;
                wmma::load_matrix_sync(b_hi[j], Bhi + n0 * GW_LD + k0, GW_LD);
                wmma::load_matrix_sync(b_lo[j], Blo + n0 * GW_LD + k0, GW_LD);
            }
            #pragma unroll
            for (int i = 0; i < 2; i++)
                #pragma unroll
                for (int j = 0; j < 2; j++) {
                    wmma::mma_sync(acc[i][j], a_hi[i], b_hi[j], acc[i][j]);
                    wmma::mma_sync(acc[i][j], a_hi[i], b_lo[j], acc[i][j]);
                    wmma::mma_sync(acc[i][j], a_lo[i], b_hi[j], acc[i][j]);
                }
        }
        __syncthreads();   // all reads done before next fill overwrites tiles
    }

    // stage accumulators to SMEM (reuse tile memory), then fused bias+PReLU writeout
    float* stage = (float*)dsm;
    #pragma unroll
    for (int i = 0; i < 2; i++)
        #pragma unroll
        for (int j = 0; j < 2; j++) {
            int r0 = warp_m * 32 + i * 16;
            int n0 = warp_n * 32 + j * 16;
            wmma::store_matrix_sync(stage + r0 * GW_SLD + n0, acc[i][j], GW_SLD,
                                    wmma::mem_row_major);
        }
    __syncthreads();

    // writeout: 128 rows x 64 cols = 2048 float4-groups, 8 per thread
    #pragma unroll 4
    for (int it = 0; it < 8; it++) {
        int g  = tid + it * 256;
        int r  = g >> 4;                  // 0..127
        int c0 = (g & 15) << 2;           // 0..60
        int grow = block_row + r;
        if (grow < M) {
            float4 v  = *(const float4*)(stage + r * GW_SLD + c0);
            float4 bb = *(const float4*)(bl + nbase + c0);
            float4 aa = *(const float4*)(pa + nbase + c0);
            float v0 = v.x + bb.x, v1 = v.y + bb.y, v2 = v.z + bb.z, v3 = v.w + bb.w;
            float4 o;
            o.x = (v0 > 0.f) ? v0 : aa.x * v0;
            o.y = (v1 > 0.f) ? v1 : aa.y * v1;
            o.z = (v2 > 0.f) ? v2 : aa.z * v2;
            o.w = (v3 > 0.f) ? v3 : aa.w * v3;
            *(float4*)(O + (size_t)grow * CH + nbase + c0) = o;
        }
    }
}

// ---------------- launch ----------------
extern "C" void kernel_launch(void* const* d_in, const int* in_sizes, int n_in,
                              void* d_out, int out_size) {
    const float* x    = (const float*)d_in[0];
    const int*   ei32 = (const int*)d_in[1];
    int wb = n_in - 12;                          // weights are the LAST 12 inputs
    const float* Wl0 = (const float*)d_in[wb + 0];
    const float* bl0 = (const float*)d_in[wb + 1];
    const float* Wr0 = (const float*)d_in[wb + 2];
    const float* a0  = (const float*)d_in[wb + 3];
    const float* Wl1 = (const float*)d_in[wb + 4];
    const float* bl1 = (const float*)d_in[wb + 5];
    const float* Wr1 = (const float*)d_in[wb + 6];
    const float* a1  = (const float*)d_in[wb + 7];
    const float* Wl2 = (const float*)d_in[wb + 8];
    const float* bl2 = (const float*)d_in[wb + 9];
    const float* Wr2 = (const float*)d_in[wb + 10];
    const float* a2  = (const float*)d_in[wb + 11];
    float* out = (float*)d_out;

    const int EB = (N_EDGES + 255) / 256;        // 3125
    const int NB = (N_NODES + 255) / 256;        // 196
    const int GM = (N_NODES + 127) / 128;        // 391

    cudaFuncSetAttribute(gemm_wmma_kernel,
                         cudaFuncAttributeMaxDynamicSharedMemorySize, GW_SMEM);

    // CSR build
    init_kernel<<<NB + 1, 256>>>(ei32);          // #0
    hist_kernel<<<EB, 256>>>(ei32);              // #1
    scan_kernel<<<SCAN_BLOCKS, SCAN_CHUNK>>>();  // #2
    fill_kernel<<<EB, 256>>>(ei32);              // #3

    // Layer 1
    agg_kernel<<<(N_NODES + 7) / 8, 256>>>(x, 0, N_NODES);                               // #4
    gemm_wmma_kernel<<<dim3(GM, 2), 256, GW_SMEM>>>(x, 0, Wl0, bl0, Wr0, a0, nullptr, 1, N_NODES);  // #5 <- profiled

    // Layer 2
    agg_kernel<<<(N_NODES + 7) / 8, 256>>>(nullptr, 1, N_NODES);
    gemm_wmma_kernel<<<dim3(GM, 2), 256, GW_SMEM>>>(nullptr, 1, Wl1, bl1, Wr1, a1, nullptr, 2, N_NODES);

    // Layer 3: only rows < 1024 needed
    agg_kernel<<<1024 / 8, 256>>>(nullptr, 2, 1024);
    gemm_wmma_kernel<<<dim3(1024 / 128, 2), 256, GW_SMEM>>>(nullptr, 2, Wl2, bl2, Wr2, a2, out, 0, 1024);
}